// round 6
// baseline (speedup 1.0000x reference)
#include <cuda_runtime.h>
#include <cuda_fp16.h>
#include <cstdint>
#include <cstddef>

#define M_TOTAL 8192
#define IN_F    4096
#define OUT_F   11008
#define BM      128
#define BN      128
#define BK      64                  /* fp16 K per chunk */
#define NCH     (IN_F / BK)         /* 64 */
#define GT      256                 /* 8 warps: 4(m) x 2(n), 32x64 warp tiles */

#define STRIDE  144                 /* bytes per smem row (72 halves, pad) */
#define S_A     0
#define S_B     (BM * STRIDE)       /* 18432 */
#define S_STAGE (2 * BM * STRIDE)   /* 36864 */
#define SMEM_T  (2 * S_STAGE)       /* 73728 */

/* fp16 scratch (__device__ globals: alloc-free rule) */
__device__ __half g_xh[(size_t)M_TOTAL * IN_F];
__device__ __half g_wh[(size_t)OUT_F * IN_F];

static __device__ __forceinline__ uint32_t smem_u32(const void* p) {
    uint32_t a;
    asm("{ .reg .u64 t; cvta.to.shared.u64 t, %1; cvt.u32.u64 %0, t; }"
        : "=r"(a) : "l"(p));
    return a;
}

static __device__ __forceinline__ void cp16(uint32_t dst, const void* src) {
    asm volatile("cp.async.cg.shared.global [%0], [%1], 16;"
                 :: "r"(dst), "l"(src) : "memory");
}

static __device__ __forceinline__ void ldm_x4(uint32_t* r, uint32_t a) {
    asm volatile("ldmatrix.sync.aligned.m8n8.x4.shared.b16 {%0,%1,%2,%3}, [%4];"
                 : "=r"(r[0]), "=r"(r[1]), "=r"(r[2]), "=r"(r[3]) : "r"(a));
}

static __device__ __forceinline__ void mma16816(float* d, const uint32_t* a,
                                                const uint32_t* b) {
    asm volatile(
        "mma.sync.aligned.m16n8k16.row.col.f32.f16.f16.f32 "
        "{%0,%1,%2,%3}, {%4,%5,%6,%7}, {%8,%9}, {%0,%1,%2,%3};"
        : "+f"(d[0]), "+f"(d[1]), "+f"(d[2]), "+f"(d[3])
        : "r"(a[0]), "r"(a[1]), "r"(a[2]), "r"(a[3]), "r"(b[0]), "r"(b[1]));
}

/* ---------------- phase 1: fused fp16 conversions ---------------- */

#define NX4 ((long)M_TOTAL * IN_F / 4)    /* 8388608  */
#define NW4 ((long)OUT_F * IN_F / 4)      /* 11272192 */

__global__ void k_convert(const float* __restrict__ x, const int* __restrict__ wq) {
    const long stride = (long)gridDim.x * blockDim.x;
    for (long i = (long)blockIdx.x * blockDim.x + threadIdx.x; i < NX4 + NW4;
         i += stride) {
        if (i < NX4) {
            float4 v = ((const float4*)x)[i];
            __half2* p = (__half2*)g_xh;
            p[2 * i]     = __floats2half2_rn(v.x, v.y);
            p[2 * i + 1] = __floats2half2_rn(v.z, v.w);
        } else {
            const long j = i - NX4;
            int4 w = ((const int4*)wq)[j];
            __half2* p = (__half2*)g_wh;
            __half2 t;
            t.x = __int2half_rn(w.x); t.y = __int2half_rn(w.y);
            p[2 * j] = t;
            t.x = __int2half_rn(w.z); t.y = __int2half_rn(w.w);
            p[2 * j + 1] = t;
        }
    }
}

/* ---------------- phase 2: fp16 HMMA GEMM, frag double-buffer ----------- */

static __device__ __forceinline__ void loadfrags(
    uint32_t st, int ke, int wm, int wn, int a_row, int a_koff,
    int b_row, int b_koff, uint32_t af[2][4], uint32_t* bf) {
#pragma unroll
    for (int mf = 0; mf < 2; mf++)
        ldm_x4(af[mf], st + S_A + (uint32_t)(wm + 16 * mf + a_row) * STRIDE
                         + (ke + a_koff) * 2);
#pragma unroll
    for (int g = 0; g < 4; g++)
        ldm_x4(&bf[g * 4], st + S_B + (uint32_t)(wn + 16 * g + b_row) * STRIDE
                             + (ke + b_koff) * 2);
}

__global__ void __launch_bounds__(GT, 1)
gemm_kernel(float* __restrict__ out, const float* __restrict__ ws) {
    extern __shared__ char smem[];
    const uint32_t sb = smem_u32(smem);
    const int tid = threadIdx.x;
    const int wid = tid >> 5;
    const int lid = tid & 31;
    const int n0 = blockIdx.x * BN;
    const int m0 = blockIdx.y * BM;

    /* warps 4(m) x 2(n): warp tile 32 x 64 */
    const int wm = (wid & 3) * 32;
    const int wn = (wid >> 2) * 64;

    /* cp.async: 2 threads per 128B row, 64B each */
    const int r = tid >> 1, half = tid & 1;
    const __half* gA = g_xh + (size_t)(m0 + r) * IN_F + half * 32;
    const __half* gB = g_wh + (size_t)(n0 + r) * IN_F + half * 32;
    const uint32_t dst = (uint32_t)r * STRIDE + half * 64;

    const int a_row  = (lid & 7) + ((lid >> 3) & 1) * 8;
    const int a_koff = (lid >> 4) * 8;
    const int b_row  = (lid & 7) + ((lid >> 4) & 1) * 8;
    const int b_koff = ((lid >> 3) & 1) * 8;

    float acc[2][8][4];
#pragma unroll
    for (int mf = 0; mf < 2; mf++)
#pragma unroll
        for (int nf = 0; nf < 8; nf++)
#pragma unroll
            for (int j = 0; j < 4; j++) acc[mf][nf][j] = 0.0f;

    /* prefetch chunk 0 */
#pragma unroll
    for (int i = 0; i < 4; i++) {
        cp16(sb + S_A + dst + i * 16, gA + i * 8);
        cp16(sb + S_B + dst + i * 16, gB + i * 8);
    }
    asm volatile("cp.async.commit_group;" ::: "memory");

    for (int c = 0; c < NCH; c++) {
        if (c + 1 < NCH) {
            const uint32_t st = sb + ((c + 1) & 1) * S_STAGE;
            const long ko = (long)(c + 1) * BK;
#pragma unroll
            for (int i = 0; i < 4; i++) {
                cp16(st + S_A + dst + i * 16, gA + ko + i * 8);
                cp16(st + S_B + dst + i * 16, gB + ko + i * 8);
            }
            asm volatile("cp.async.commit_group;" ::: "memory");
            asm volatile("cp.async.wait_group 1;" ::: "memory");
        } else {
            asm volatile("cp.async.wait_group 0;" ::: "memory");
        }
        __syncthreads();

        const uint32_t st = sb + (c & 1) * S_STAGE;

        /* fragment double-buffer: load kk+1 while issuing kk's MMAs */
        uint32_t af[2][2][4], bf[2][16];
        loadfrags(st, 0, wm, wn, a_row, a_koff, b_row, b_koff, af[0], bf[0]);
#pragma unroll
        for (int kk = 0; kk < 4; kk++) {
            const int cur = kk & 1, nxt = cur ^ 1;
            if (kk < 3)
                loadfrags(st, (kk + 1) * 16, wm, wn, a_row, a_koff,
                          b_row, b_koff, af[nxt], bf[nxt]);
#pragma unroll
            for (int mf = 0; mf < 2; mf++)
#pragma unroll
                for (int nf = 0; nf < 8; nf++) {
                    const uint32_t* bp = &bf[cur][(nf >> 1) * 4 + (nf & 1) * 2];
                    mma16816(acc[mf][nf], af[cur][mf], bp);
                }
        }
        __syncthreads();
    }

    /* epilogue: y = acc * ws[n] */
#pragma unroll
    for (int nf = 0; nf < 8; nf++) {
        const int n = n0 + wn + nf * 8 + 2 * (lid & 3);
        const float s0 = __ldg(ws + n);
        const float s1 = __ldg(ws + n + 1);
#pragma unroll
        for (int mf = 0; mf < 2; mf++) {
            const int mrow = m0 + wm + 16 * mf + (lid >> 2);
            float2 v0, v1;
            v0.x = acc[mf][nf][0] * s0;
            v0.y = acc[mf][nf][1] * s1;
            v1.x = acc[mf][nf][2] * s0;
            v1.y = acc[mf][nf][3] * s1;
            *(float2*)(out + (size_t)mrow * OUT_F + n) = v0;
            *(float2*)(out + (size_t)(mrow + 8) * OUT_F + n) = v1;
        }
    }
}

extern "C" void kernel_launch(void* const* d_in, const int* in_sizes, int n_in,
                              void* d_out, int out_size) {
    const float* x  = (const float*)d_in[0];
    const int*   wq = (const int*)d_in[1];
    const float* ws = (const float*)d_in[2];
    float* out = (float*)d_out;

    cudaFuncSetAttribute(gemm_kernel, cudaFuncAttributeMaxDynamicSharedMemorySize,
                         SMEM_T);

    k_convert<<<8192, 256>>>(x, wq);

    dim3 grid(OUT_F / BN, M_TOTAL / BM);   /* 86 x 64 */
    gemm_kernel<<<grid, GT, SMEM_T>>>(out, ws);
}

// round 7
// speedup vs baseline: 1.2838x; 1.2838x over previous
#include <cuda_runtime.h>
#include <cuda_fp16.h>
#include <cstdint>
#include <cstddef>

#define M_TOTAL 8192
#define IN_F    4096
#define OUT_F   11008
#define BM      128
#define BN      128
#define BK      64                  /* fp16 K per chunk */
#define NCH     (IN_F / BK)         /* 64 */
#define GT      256                 /* 8 warps: 4(m) x 2(n), 32x64 warp tiles */

#define STRIDE  144                 /* bytes per smem row (72 halves, pad) */
#define S_A     0
#define S_B     (BM * STRIDE)       /* 18432 */
#define S_STAGE (2 * BM * STRIDE)   /* 36864 */
#define SMEM_T  (3 * S_STAGE)       /* 110592: 3-stage pipeline */

/* fp16 scratch (__device__ globals: alloc-free rule) */
__device__ __half g_xh[(size_t)M_TOTAL * IN_F];
__device__ __half g_wh[(size_t)OUT_F * IN_F];

static __device__ __forceinline__ uint32_t smem_u32(const void* p) {
    uint32_t a;
    asm("{ .reg .u64 t; cvta.to.shared.u64 t, %1; cvt.u32.u64 %0, t; }"
        : "=r"(a) : "l"(p));
    return a;
}

static __device__ __forceinline__ void cp16(uint32_t dst, const void* src) {
    asm volatile("cp.async.cg.shared.global [%0], [%1], 16;"
                 :: "r"(dst), "l"(src) : "memory");
}

static __device__ __forceinline__ void ldm_x4(uint32_t* r, uint32_t a) {
    asm volatile("ldmatrix.sync.aligned.m8n8.x4.shared.b16 {%0,%1,%2,%3}, [%4];"
                 : "=r"(r[0]), "=r"(r[1]), "=r"(r[2]), "=r"(r[3]) : "r"(a));
}

static __device__ __forceinline__ void mma16816(float* d, const uint32_t* a,
                                                const uint32_t* b) {
    asm volatile(
        "mma.sync.aligned.m16n8k16.row.col.f32.f16.f16.f32 "
        "{%0,%1,%2,%3}, {%4,%5,%6,%7}, {%8,%9}, {%0,%1,%2,%3};"
        : "+f"(d[0]), "+f"(d[1]), "+f"(d[2]), "+f"(d[3])
        : "r"(a[0]), "r"(a[1]), "r"(a[2]), "r"(a[3]), "r"(b[0]), "r"(b[1]));
}

/* ---------------- phase 1: fused fp16 conversions ---------------- */

#define NX4 ((long)M_TOTAL * IN_F / 4)    /* 8388608  */
#define NW4 ((long)OUT_F * IN_F / 4)      /* 11272192 */

__global__ void k_convert(const float* __restrict__ x, const int* __restrict__ wq) {
    const long stride = (long)gridDim.x * blockDim.x;
    for (long i = (long)blockIdx.x * blockDim.x + threadIdx.x; i < NX4 + NW4;
         i += stride) {
        if (i < NX4) {
            float4 v = ((const float4*)x)[i];
            __half2* p = (__half2*)g_xh;
            p[2 * i]     = __floats2half2_rn(v.x, v.y);
            p[2 * i + 1] = __floats2half2_rn(v.z, v.w);
        } else {
            const long j = i - NX4;
            int4 w = ((const int4*)wq)[j];
            __half2* p = (__half2*)g_wh;
            __half2 t;
            t.x = __int2half_rn(w.x); t.y = __int2half_rn(w.y);
            p[2 * j] = t;
            t.x = __int2half_rn(w.z); t.y = __int2half_rn(w.w);
            p[2 * j + 1] = t;
        }
    }
}

/* ---------------- phase 2: fp16 HMMA GEMM, 3-stage pipeline ------------- */

__global__ void __launch_bounds__(GT, 2)
gemm_kernel(float* __restrict__ out, const float* __restrict__ ws) {
    extern __shared__ char smem[];
    const uint32_t sb = smem_u32(smem);
    const int tid = threadIdx.x;
    const int wid = tid >> 5;
    const int lid = tid & 31;
    const int n0 = blockIdx.x * BN;
    const int m0 = blockIdx.y * BM;

    /* warps 4(m) x 2(n): warp tile 32 x 64 */
    const int wm = (wid & 3) * 32;
    const int wn = (wid >> 2) * 64;

    /* cp.async: 2 threads per 128B row, 64B each */
    const int r = tid >> 1, half = tid & 1;
    const __half* gA = g_xh + (size_t)(m0 + r) * IN_F + half * 32;
    const __half* gB = g_wh + (size_t)(n0 + r) * IN_F + half * 32;
    const uint32_t dst = (uint32_t)r * STRIDE + half * 64;

    const int a_row  = (lid & 7) + ((lid >> 3) & 1) * 8;
    const int a_koff = (lid >> 4) * 8;
    const int b_row  = (lid & 7) + ((lid >> 4) & 1) * 8;
    const int b_koff = ((lid >> 3) & 1) * 8;

    float acc[2][8][4];
#pragma unroll
    for (int mf = 0; mf < 2; mf++)
#pragma unroll
        for (int nf = 0; nf < 8; nf++)
#pragma unroll
            for (int j = 0; j < 4; j++) acc[mf][nf][j] = 0.0f;

    /* prologue: prefetch chunks 0 and 1 into stages 0,1 */
#pragma unroll
    for (int i = 0; i < 4; i++) {
        cp16(sb + S_A + dst + i * 16, gA + i * 8);
        cp16(sb + S_B + dst + i * 16, gB + i * 8);
    }
    asm volatile("cp.async.commit_group;" ::: "memory");
#pragma unroll
    for (int i = 0; i < 4; i++) {
        cp16(sb + S_STAGE + S_A + dst + i * 16, gA + BK + i * 8);
        cp16(sb + S_STAGE + S_B + dst + i * 16, gB + BK + i * 8);
    }
    asm volatile("cp.async.commit_group;" ::: "memory");

    int bc = 0;   /* stage of chunk c   */
    int bn2 = 2;  /* stage of chunk c+2 */

    for (int c = 0; c < NCH; c++) {
        if (c < NCH - 1) {
            asm volatile("cp.async.wait_group 1;" ::: "memory");
        } else {
            asm volatile("cp.async.wait_group 0;" ::: "memory");
        }
        __syncthreads();

        /* prefetch chunk c+2 into stage bn2 (its last readers were iter c-1,
           all warps are past this iteration's sync -> safe, no trailing sync) */
        if (c + 2 < NCH) {
            const uint32_t st = sb + bn2 * S_STAGE;
            const long ko = (long)(c + 2) * BK;
#pragma unroll
            for (int i = 0; i < 4; i++) {
                cp16(st + S_A + dst + i * 16, gA + ko + i * 8);
                cp16(st + S_B + dst + i * 16, gB + ko + i * 8);
            }
            asm volatile("cp.async.commit_group;" ::: "memory");
        }

        const uint32_t st = sb + bc * S_STAGE;
#pragma unroll
        for (int kk = 0; kk < 4; kk++) {
            const int ke = kk * 16;
            uint32_t ah[2][4], bb[16];
#pragma unroll
            for (int mf = 0; mf < 2; mf++) {
                uint32_t base = st + S_A + (uint32_t)(wm + 16 * mf + a_row) * STRIDE
                                + (ke + a_koff) * 2;
                ldm_x4(ah[mf], base);
            }
#pragma unroll
            for (int nf4 = 0; nf4 < 4; nf4++) {
                uint32_t addr = st + S_B + (uint32_t)(wn + 16 * nf4 + b_row) * STRIDE
                                + (ke + b_koff) * 2;
                ldm_x4(&bb[nf4 * 4], addr);
            }
#pragma unroll
            for (int mf = 0; mf < 2; mf++)
#pragma unroll
                for (int nf = 0; nf < 8; nf++) {
                    const uint32_t* bp = &bb[(nf >> 1) * 4 + (nf & 1) * 2];
                    mma16816(acc[mf][nf], ah[mf], bp);
                }
        }
        bc  = (bc  == 2) ? 0 : bc + 1;
        bn2 = (bn2 == 2) ? 0 : bn2 + 1;
    }

    /* epilogue: y = acc * ws[n] */
#pragma unroll
    for (int nf = 0; nf < 8; nf++) {
        const int n = n0 + wn + nf * 8 + 2 * (lid & 3);
        const float s0 = __ldg(ws + n);
        const float s1 = __ldg(ws + n + 1);
#pragma unroll
        for (int mf = 0; mf < 2; mf++) {
            const int mrow = m0 + wm + 16 * mf + (lid >> 2);
            float2 v0, v1;
            v0.x = acc[mf][nf][0] * s0;
            v0.y = acc[mf][nf][1] * s1;
            v1.x = acc[mf][nf][2] * s0;
            v1.y = acc[mf][nf][3] * s1;
            *(float2*)(out + (size_t)mrow * OUT_F + n) = v0;
            *(float2*)(out + (size_t)(mrow + 8) * OUT_F + n) = v1;
        }
    }
}

extern "C" void kernel_launch(void* const* d_in, const int* in_sizes, int n_in,
                              void* d_out, int out_size) {
    const float* x  = (const float*)d_in[0];
    const int*   wq = (const int*)d_in[1];
    const float* ws = (const float*)d_in[2];
    float* out = (float*)d_out;

    cudaFuncSetAttribute(gemm_kernel, cudaFuncAttributeMaxDynamicSharedMemorySize,
                         SMEM_T);

    k_convert<<<8192, 256>>>(x, wq);

    dim3 grid(OUT_F / BN, M_TOTAL / BM);   /* 86 x 64 */
    gemm_kernel<<<grid, GT, SMEM_T>>>(out, ws);
}